// round 13
// baseline (speedup 1.0000x reference)
#include <cuda_runtime.h>
#include <cstddef>

// Problem constants
#define Bsz   16384
#define Xlen  50
#define CINd  128
#define Hdim  128
#define NG3   384           // 3*H
#define NGEMM 512           // 3*H + H  (gates | alpha_ih)

// Scratch (device globals — no allocation in kernel_launch)
__device__ float d_P[(size_t)Bsz * NGEMM];     // inp @ [W_ih | aW_ih], 33.5 MB
__device__ float d_Wpack[CINd * NGEMM];        // packed weights
__device__ int   d_mismatch[2];                // [0]: w_hh != tile(eye,(1,3)), [1]: aw_hh != eye

// ---------------------------------------------------------------------------
// Kernel 1: verify identity structure of recurrent weights + pack input weights
// ---------------------------------------------------------------------------
__global__ void check_pack_kernel(const float* __restrict__ w_ih,
                                  const float* __restrict__ w_hh,
                                  const float* __restrict__ aw_ih,
                                  const float* __restrict__ aw_hh) {
    int tid = blockIdx.x * blockDim.x + threadIdx.x;
    int nth = gridDim.x * blockDim.x;

    // weight_hh == tile(eye(H), (1,3)) ?   shape [CIN=128, 384]
    bool bad = false;
    for (int idx = tid; idx < CINd * NG3; idx += nth) {
        int k = idx / NG3, j = idx % NG3;
        float ev = ((j & (Hdim - 1)) == k) ? 1.0f : 0.0f;
        if (w_hh[idx] != ev) bad = true;
    }
    if (bad) atomicOr(&d_mismatch[0], 1);

    // alpha_weight_hh == eye(H) ?   shape [128, 128]
    bad = false;
    for (int idx = tid; idx < Hdim * Hdim; idx += nth) {
        int k = idx / Hdim, j = idx % Hdim;
        float ev = (j == k) ? 1.0f : 0.0f;
        if (aw_hh[idx] != ev) bad = true;
    }
    if (bad) atomicOr(&d_mismatch[1], 1);

    // pack [CIN, 512] = [ weight_ih (384) | alpha_weight_ih (128) ]
    for (int idx = tid; idx < CINd * NGEMM; idx += nth) {
        int k = idx / NGEMM, j = idx % NGEMM;
        d_Wpack[idx] = (j < NG3) ? w_ih[k * NG3 + j]
                                 : aw_ih[k * Hdim + (j - NG3)];
    }
}

// ---------------------------------------------------------------------------
// Kernel 2: fp32 tiled GEMM   P[16384,512] = inp[16384,128] @ Wpack[128,512]
// 128x128 tile per block, 256 threads, 8x8 outputs per thread.
// ---------------------------------------------------------------------------
#define BM 128
#define BN 128
#define BK 32

__global__ __launch_bounds__(256)
void gemm_kernel(const float* __restrict__ A) {
    __shared__ float As[BM][BK + 1];   // [m][k], padded: conflict-free stores
    __shared__ float Bs[BK][BN];       // [k][n]

    const int m0 = blockIdx.x * BM;
    const int n0 = blockIdx.y * BN;
    const int tid = threadIdx.x;
    const int tm = tid >> 4;           // 0..15
    const int tn = tid & 15;           // 0..15

    float acc[8][8];
#pragma unroll
    for (int i = 0; i < 8; i++)
#pragma unroll
        for (int j = 0; j < 8; j++) acc[i][j] = 0.0f;

    for (int k0 = 0; k0 < CINd; k0 += BK) {
        // Load A tile: 128x32 scalars, lane -> k (coalesced, conflict-free STS)
#pragma unroll
        for (int it = 0; it < 16; it++) {
            int idx = it * 256 + tid;
            int k = idx & 31;
            int m = idx >> 5;
            As[m][k] = A[(size_t)(m0 + m) * CINd + k0 + k];
        }
        // Load B tile: 32x128, lane -> n (coalesced, conflict-free)
#pragma unroll
        for (int it = 0; it < 16; it++) {
            int idx = it * 256 + tid;
            int n = idx & 127;
            int r = idx >> 7;
            Bs[r][n] = d_Wpack[(k0 + r) * NGEMM + n0 + n];
        }
        __syncthreads();

#pragma unroll
        for (int kk = 0; kk < BK; kk++) {
            float a[8], bf[8];
#pragma unroll
            for (int i = 0; i < 8; i++) a[i] = As[tm * 8 + i][kk];
            float4 b0 = *(const float4*)&Bs[kk][tn * 8];
            float4 b1 = *(const float4*)&Bs[kk][tn * 8 + 4];
            bf[0] = b0.x; bf[1] = b0.y; bf[2] = b0.z; bf[3] = b0.w;
            bf[4] = b1.x; bf[5] = b1.y; bf[6] = b1.z; bf[7] = b1.w;
#pragma unroll
            for (int i = 0; i < 8; i++)
#pragma unroll
                for (int j = 0; j < 8; j++)
                    acc[i][j] = fmaf(a[i], bf[j], acc[i][j]);
        }
        __syncthreads();
    }

    // Store 8x8 per thread, vectorized
#pragma unroll
    for (int i = 0; i < 8; i++) {
        size_t base = (size_t)(m0 + tm * 8 + i) * NGEMM + n0 + tn * 8;
        *(float4*)&d_P[base]     = make_float4(acc[i][0], acc[i][1], acc[i][2], acc[i][3]);
        *(float4*)&d_P[base + 4] = make_float4(acc[i][4], acc[i][5], acc[i][6], acc[i][7]);
    }
}

// ---------------------------------------------------------------------------
// Kernel 3: fused skip-softmax-LSTM. One block per batch row, 128 threads.
// ---------------------------------------------------------------------------
__device__ __forceinline__ float fsigmoid(float z) {
    return __fdividef(1.0f, 1.0f + __expf(-z));
}

__global__ __launch_bounds__(128)
void main_kernel(const float* __restrict__ skip_c,
                 const int*   __restrict__ skip_count,
                 const float* __restrict__ h0,
                 const float* __restrict__ w_hh,
                 const float* __restrict__ bias,
                 const float* __restrict__ aw_hh,
                 const float* __restrict__ a_bias,
                 float* __restrict__ out) {
    __shared__ float sh[Hdim];

    const int b = blockIdx.x;
    const int h = threadIdx.x;
    const int cnt = skip_count[b];

    const float* P = d_P + (size_t)b * NGEMM;
    const float* srow = skip_c + (size_t)b * Xlen * Hdim;

    const float pre = P[NG3 + h] + a_bias[h];   // alpha_ih + alpha_bias

    float denom = 0.0f, num = 0.0f;

    if (d_mismatch[1] == 0) {
        // FAST PATH: alpha_weight_hh == I  =>  skip @ aW_hh == skip
        int x = 0;
        for (; x + 4 <= cnt; x += 4) {
            float s0 = srow[(x + 0) * Hdim + h];
            float s1 = srow[(x + 1) * Hdim + h];
            float s2 = srow[(x + 2) * Hdim + h];
            float s3 = srow[(x + 3) * Hdim + h];
            float e0 = __expf(fsigmoid(pre + s0));
            float e1 = __expf(fsigmoid(pre + s1));
            float e2 = __expf(fsigmoid(pre + s2));
            float e3 = __expf(fsigmoid(pre + s3));
            denom += (e0 + e1) + (e2 + e3);
            num = fmaf(s0, e0, num); num = fmaf(s1, e1, num);
            num = fmaf(s2, e2, num); num = fmaf(s3, e3, num);
        }
        for (; x < cnt; x++) {
            float s = srow[x * Hdim + h];
            float e = __expf(fsigmoid(pre + s));
            denom += e;
            num = fmaf(s, e, num);
        }
    } else {
        // GENERIC PATH (correctness fallback): full matvec per skip row
        for (int x = 0; x < cnt; x++) {
            __syncthreads();
            sh[h] = srow[x * Hdim + h];
            __syncthreads();
            float accm = 0.0f;
#pragma unroll 8
            for (int k = 0; k < Hdim; k++)
                accm = fmaf(sh[k], aw_hh[k * Hdim + h], accm);
            float s = sh[h];
            float e = __expf(fsigmoid(pre + accm));
            denom += e;
            num = fmaf(s, e, num);
        }
    }

    // gates: recurrent contribution
    float hh0, hh1, hh2;
    if (d_mismatch[0] == 0) {
        // FAST PATH: weight_hh == tile(I,(1,3))  =>  h0 broadcast into all gates
        float hv = h0[(size_t)b * Hdim + h];
        hh0 = hh1 = hh2 = hv;
    } else {
        __syncthreads();
        sh[h] = h0[(size_t)b * Hdim + h];
        __syncthreads();
        hh0 = hh1 = hh2 = 0.0f;
        for (int k = 0; k < Hdim; k++) {
            float hv = sh[k];
            hh0 = fmaf(hv, w_hh[k * NG3 + h], hh0);
            hh1 = fmaf(hv, w_hh[k * NG3 + Hdim + h], hh1);
            hh2 = fmaf(hv, w_hh[k * NG3 + 2 * Hdim + h], hh2);
        }
    }

    float gi = P[h]            + hh0 + bias[h];
    float go = P[Hdim + h]     + hh1 + bias[Hdim + h];
    float gg = P[2 * Hdim + h] + hh2 + bias[2 * Hdim + h];

    float iv = fsigmoid(gi);
    float ov = fsigmoid(go);
    float gv = tanhf(gg);
    float ei = __expf(iv);

    float c1 = __fdividef(fmaf(gv, ei, num), ei + denom);
    float h1 = ov * tanhf(c1);

    out[(size_t)b * Hdim + h] = h1;                                // h_1 first
    out[(size_t)Bsz * Hdim + (size_t)b * Hdim + h] = c1;           // c_1 second
}

// ---------------------------------------------------------------------------
// kernel_launch
// Input order (metadata): inp, skip_c, skip_count, h0, c0, weight_ih,
//                         weight_hh, bias, alpha_weight_ih, alpha_weight_hh,
//                         alpha_bias.   Output: [h_1 (B*H) ; c_1 (B*H)] fp32.
// ---------------------------------------------------------------------------
extern "C" void kernel_launch(void* const* d_in, const int* in_sizes, int n_in,
                              void* d_out, int out_size) {
    const float* inp        = (const float*)d_in[0];
    const float* skip_c     = (const float*)d_in[1];
    const int*   skip_count = (const int*)  d_in[2];
    const float* h0         = (const float*)d_in[3];
    // d_in[4] = c0 : unused by the reference
    const float* w_ih       = (const float*)d_in[5];
    const float* w_hh       = (const float*)d_in[6];
    const float* bias       = (const float*)d_in[7];
    const float* aw_ih      = (const float*)d_in[8];
    const float* aw_hh      = (const float*)d_in[9];
    const float* a_bias     = (const float*)d_in[10];
    float* out = (float*)d_out;

    void* pmis = nullptr;
    cudaGetSymbolAddress(&pmis, d_mismatch);
    cudaMemsetAsync(pmis, 0, 2 * sizeof(int));

    check_pack_kernel<<<64, 256>>>(w_ih, w_hh, aw_ih, aw_hh);
    gemm_kernel<<<dim3(Bsz / BM, NGEMM / BN), 256>>>(inp);
    main_kernel<<<Bsz, Hdim>>>(skip_c, skip_count, h0, w_hh, bias,
                               aw_hh, a_bias, out);
}

// round 14
// speedup vs baseline: 1.0676x; 1.0676x over previous
#include <cuda_runtime.h>
#include <cstddef>

// Problem constants
#define Bsz   16384
#define Xlen  50
#define CINd  128
#define Hdim  128
#define NG3   384           // 3*H
#define NGEMM 512           // 3*H + H  (gates | alpha_ih)

// Scratch (device globals — no allocation in kernel_launch)
__device__ float d_P[(size_t)Bsz * NGEMM];     // inp @ [W_ih | aW_ih], 33.5 MB
__device__ int   d_mismatch[2];                // [0]: w_hh != tile(eye,(1,3)), [1]: aw_hh != eye

// ---------------------------------------------------------------------------
// f32x2 packed-FMA helpers (ptxas never emits FFMA2 from C++; PTX only)
// ---------------------------------------------------------------------------
__device__ __forceinline__ void ffma2(unsigned long long& d,
                                      unsigned long long a,
                                      unsigned long long b) {
    asm("fma.rn.f32x2 %0, %1, %2, %0;" : "+l"(d) : "l"(a), "l"(b));
}
__device__ __forceinline__ unsigned long long pack2(float x, float y) {
    unsigned long long r;
    asm("mov.b64 %0, {%1, %2};" : "=l"(r) : "f"(x), "f"(y));
    return r;
}
__device__ __forceinline__ float2 unpack2(unsigned long long u) {
    float2 r;
    asm("mov.b64 {%0, %1}, %2;" : "=f"(r.x), "=f"(r.y) : "l"(u));
    return r;
}

// ---------------------------------------------------------------------------
// Kernel 1: verify identity structure of recurrent weights (vectorized)
//   w_hh  : [128, 384] should equal tile(eye(128), (1,3))
//   aw_hh : [128, 128] should equal eye(128)
// 16384 float4 elements total; one per thread, grid 64x256.
// ---------------------------------------------------------------------------
__global__ __launch_bounds__(256)
void check_kernel(const float* __restrict__ w_hh,
                  const float* __restrict__ aw_hh) {
    int idx = blockIdx.x * 256 + threadIdx.x;   // float4 index
    if (idx < 12288) {
        float4 v = reinterpret_cast<const float4*>(w_hh)[idx];
        int f = idx * 4;
        int k = f / NG3;
        int c = f - k * NG3;           // 384 % 4 == 0 -> never crosses a row
        bool bad = (v.x != ((((c    ) & 127) == k) ? 1.f : 0.f))
                 | (v.y != ((((c + 1) & 127) == k) ? 1.f : 0.f))
                 | (v.z != ((((c + 2) & 127) == k) ? 1.f : 0.f))
                 | (v.w != ((((c + 3) & 127) == k) ? 1.f : 0.f));
        if (bad) atomicOr(&d_mismatch[0], 1);
    } else {
        int j = idx - 12288;           // 0..4095
        float4 v = reinterpret_cast<const float4*>(aw_hh)[j];
        int f = j * 4;
        int k = f >> 7;
        int c = f & 127;
        bool bad = (v.x != (((c    ) == k) ? 1.f : 0.f))
                 | (v.y != (((c + 1) == k) ? 1.f : 0.f))
                 | (v.z != (((c + 2) == k) ? 1.f : 0.f))
                 | (v.w != (((c + 3) == k) ? 1.f : 0.f));
        if (bad) atomicOr(&d_mismatch[1], 1);
    }
}

// ---------------------------------------------------------------------------
// Kernel 2: fp32 GEMM with packed f32x2 FMAs.
//   P[16384,512] = inp[16384,128] @ [w_ih | aw_ih]
// 128x128 tile per block, 256 threads, 8x8 outputs/thread (as 8x4 f32x2).
// A tile is stored DUPLICATED ({a,a} per element) so the inner loop needs
// no packing movs. B source selected per blockIdx.y (no weight-pack pass).
// ---------------------------------------------------------------------------
#define BM 128
#define BN 128
#define BK 32

__global__ __launch_bounds__(256)
void gemm_kernel(const float* __restrict__ A,
                 const float* __restrict__ w_ih,
                 const float* __restrict__ aw_ih) {
    __shared__ unsigned long long As2[BM][BK];   // 32 KB, {a,a} duplicated
    __shared__ float Bs[BK][BN];                 // 16 KB  (total 48 KB exactly)

    const int m0 = blockIdx.x * BM;
    const int nb = blockIdx.y;                   // 0..3
    const float* Bsrc;
    int bstride, bcol0;
    if (nb < 3) { Bsrc = w_ih;  bstride = NG3;  bcol0 = nb * BN; }
    else        { Bsrc = aw_ih; bstride = Hdim; bcol0 = 0;       }

    const int tid = threadIdx.x;
    const int tm = tid >> 4;            // 0..15
    const int tn = tid & 15;            // 0..15

    unsigned long long acc[8][4] = {};  // 8 rows x 4 f32x2 pairs (= 8x8 floats)

    for (int k0 = 0; k0 < CINd; k0 += BK) {
        // A tile: 128x32 floats = 1024 float4 loads, duplicated into As2
#pragma unroll
        for (int it = 0; it < 4; it++) {
            int idx = it * 256 + tid;
            int m = idx >> 3, kq = idx & 7;
            float4 v = *(const float4*)&A[(size_t)(m0 + m) * CINd + k0 + kq * 4];
            As2[m][kq * 4 + 0] = pack2(v.x, v.x);
            As2[m][kq * 4 + 1] = pack2(v.y, v.y);
            As2[m][kq * 4 + 2] = pack2(v.z, v.z);
            As2[m][kq * 4 + 3] = pack2(v.w, v.w);
        }
        // B tile: 32x128 floats = 1024 float4 loads (coalesced)
#pragma unroll
        for (int it = 0; it < 4; it++) {
            int idx = it * 256 + tid;
            int r = idx >> 5, nq = idx & 31;
            float4 v = *(const float4*)&Bsrc[(size_t)(k0 + r) * bstride + bcol0 + nq * 4];
            *(float4*)&Bs[r][nq * 4] = v;
        }
        __syncthreads();

#pragma unroll
        for (int kk = 0; kk < BK; kk++) {
            unsigned long long a[8], b[4];
#pragma unroll
            for (int i = 0; i < 8; i++) a[i] = As2[tm * 8 + i][kk];
            const unsigned long long* brow =
                (const unsigned long long*)&Bs[kk][tn * 8];
#pragma unroll
            for (int j = 0; j < 4; j++) b[j] = brow[j];
#pragma unroll
            for (int i = 0; i < 8; i++)
#pragma unroll
                for (int j = 0; j < 4; j++)
                    ffma2(acc[i][j], a[i], b[j]);
        }
        __syncthreads();
    }

    // Store 8x8 per thread, float4-vectorized
#pragma unroll
    for (int i = 0; i < 8; i++) {
        size_t base = (size_t)(m0 + tm * 8 + i) * NGEMM + (size_t)nb * BN + tn * 8;
        float2 f0 = unpack2(acc[i][0]);
        float2 f1 = unpack2(acc[i][1]);
        float2 f2 = unpack2(acc[i][2]);
        float2 f3 = unpack2(acc[i][3]);
        *(float4*)&d_P[base]     = make_float4(f0.x, f0.y, f1.x, f1.y);
        *(float4*)&d_P[base + 4] = make_float4(f2.x, f2.y, f3.x, f3.y);
    }
}

// ---------------------------------------------------------------------------
// Kernel 3: fused skip-softmax-LSTM. One block per batch row, 128 threads.
// Hot-loop sigmoid via MUFU.TANH (1 MUFU) instead of ex2+rcp (2 MUFU).
// ---------------------------------------------------------------------------
__device__ __forceinline__ float fsigmoid(float z) {
    float t;
    asm("tanh.approx.f32 %0, %1;" : "=f"(t) : "f"(z * 0.5f));
    return fmaf(0.5f, t, 0.5f);
}

__global__ __launch_bounds__(128)
void main_kernel(const float* __restrict__ skip_c,
                 const int*   __restrict__ skip_count,
                 const float* __restrict__ h0,
                 const float* __restrict__ w_hh,
                 const float* __restrict__ bias,
                 const float* __restrict__ aw_hh,
                 const float* __restrict__ a_bias,
                 float* __restrict__ out) {
    __shared__ float sh[Hdim];

    const int b = blockIdx.x;
    const int h = threadIdx.x;
    const int cnt = skip_count[b];

    const float* P = d_P + (size_t)b * NGEMM;
    const float* srow = skip_c + (size_t)b * Xlen * Hdim;

    const float pre = P[NG3 + h] + a_bias[h];   // alpha_ih + alpha_bias

    float denom = 0.0f, num = 0.0f;

    if (d_mismatch[1] == 0) {
        // FAST PATH: alpha_weight_hh == I  =>  skip @ aW_hh == skip
        int x = 0;
        for (; x + 4 <= cnt; x += 4) {
            float s0 = srow[(x + 0) * Hdim + h];
            float s1 = srow[(x + 1) * Hdim + h];
            float s2 = srow[(x + 2) * Hdim + h];
            float s3 = srow[(x + 3) * Hdim + h];
            float e0 = __expf(fsigmoid(pre + s0));
            float e1 = __expf(fsigmoid(pre + s1));
            float e2 = __expf(fsigmoid(pre + s2));
            float e3 = __expf(fsigmoid(pre + s3));
            denom += (e0 + e1) + (e2 + e3);
            num = fmaf(s0, e0, num); num = fmaf(s1, e1, num);
            num = fmaf(s2, e2, num); num = fmaf(s3, e3, num);
        }
        for (; x < cnt; x++) {
            float s = srow[x * Hdim + h];
            float e = __expf(fsigmoid(pre + s));
            denom += e;
            num = fmaf(s, e, num);
        }
    } else {
        // GENERIC PATH (correctness fallback): full matvec per skip row
        for (int x = 0; x < cnt; x++) {
            __syncthreads();
            sh[h] = srow[x * Hdim + h];
            __syncthreads();
            float accm = 0.0f;
#pragma unroll 8
            for (int k = 0; k < Hdim; k++)
                accm = fmaf(sh[k], aw_hh[k * Hdim + h], accm);
            float s = sh[h];
            float e = __expf(fsigmoid(pre + accm));
            denom += e;
            num = fmaf(s, e, num);
        }
    }

    // gates: recurrent contribution
    float hh0, hh1, hh2;
    if (d_mismatch[0] == 0) {
        // FAST PATH: weight_hh == tile(I,(1,3))  =>  h0 broadcast into all gates
        float hv = h0[(size_t)b * Hdim + h];
        hh0 = hh1 = hh2 = hv;
    } else {
        __syncthreads();
        sh[h] = h0[(size_t)b * Hdim + h];
        __syncthreads();
        hh0 = hh1 = hh2 = 0.0f;
        for (int k = 0; k < Hdim; k++) {
            float hv = sh[k];
            hh0 = fmaf(hv, w_hh[k * NG3 + h], hh0);
            hh1 = fmaf(hv, w_hh[k * NG3 + Hdim + h], hh1);
            hh2 = fmaf(hv, w_hh[k * NG3 + 2 * Hdim + h], hh2);
        }
    }

    float gi = P[h]            + hh0 + bias[h];
    float go = P[Hdim + h]     + hh1 + bias[Hdim + h];
    float gg = P[2 * Hdim + h] + hh2 + bias[2 * Hdim + h];

    float iv = fsigmoid(gi);
    float ov = fsigmoid(go);
    float gv = tanhf(gg);          // keep precise: only 2.1M of these
    float ei = __expf(iv);

    float c1 = __fdividef(fmaf(gv, ei, num), ei + denom);
    float h1 = ov * tanhf(c1);     // keep precise

    out[(size_t)b * Hdim + h] = h1;                                // h_1 first
    out[(size_t)Bsz * Hdim + (size_t)b * Hdim + h] = c1;           // c_1 second
}

// ---------------------------------------------------------------------------
// kernel_launch
// Input order (metadata): inp, skip_c, skip_count, h0, c0, weight_ih,
//                         weight_hh, bias, alpha_weight_ih, alpha_weight_hh,
//                         alpha_bias.   Output: [h_1 (B*H) ; c_1 (B*H)] fp32.
// ---------------------------------------------------------------------------
extern "C" void kernel_launch(void* const* d_in, const int* in_sizes, int n_in,
                              void* d_out, int out_size) {
    const float* inp        = (const float*)d_in[0];
    const float* skip_c     = (const float*)d_in[1];
    const int*   skip_count = (const int*)  d_in[2];
    const float* h0         = (const float*)d_in[3];
    // d_in[4] = c0 : unused by the reference
    const float* w_ih       = (const float*)d_in[5];
    const float* w_hh       = (const float*)d_in[6];
    const float* bias       = (const float*)d_in[7];
    const float* aw_ih      = (const float*)d_in[8];
    const float* aw_hh      = (const float*)d_in[9];
    const float* a_bias     = (const float*)d_in[10];
    float* out = (float*)d_out;

    void* pmis = nullptr;
    cudaGetSymbolAddress(&pmis, d_mismatch);
    cudaMemsetAsync(pmis, 0, 2 * sizeof(int));

    check_kernel<<<64, 256>>>(w_hh, aw_hh);
    gemm_kernel<<<dim3(Bsz / BM, NGEMM / BN), 256>>>(inp, w_ih, aw_ih);
    main_kernel<<<Bsz, Hdim>>>(skip_c, skip_count, h0, w_hh, bias,
                               aw_hh, a_bias, out);
}